// round 7
// baseline (speedup 1.0000x reference)
#include <cuda_runtime.h>

#define BB 128
#define TT 1024
#define CC 128
#define LL 128
#define EPSF 1e-7f
#define NEGF -1e30f
#define LN2F 0.69314718055994530942f
#define KSTEP 8          // DP steps per phase
#define STRIDE 48        // warp base stride = 64 - 2*KSTEP
#define RING 32          // prob rows in cp.async ring (4 phases)
#define SPAN 304         // 5*STRIDE + 64
#define NTHR 192
#define NW 6
#define LIMAX 160

__device__ __forceinline__ float ex2f(float x){ float y; asm("ex2.approx.ftz.f32 %0,%1;":"=f"(y):"f"(x)); return y; }
__device__ __forceinline__ float lg2f(float x){ float y; asm("lg2.approx.f32 %0,%1;":"=f"(y):"f"(x)); return y; }
__device__ __forceinline__ void cp16(void* s, const void* g){
    unsigned sa = (unsigned)__cvta_generic_to_shared(s);
    asm volatile("cp.async.cg.shared.global [%0],[%1],16;"::"r"(sa),"l"(g):"memory");
}
__device__ __forceinline__ void cpcommit(){ asm volatile("cp.async.commit_group;":::"memory"); }
template<int N> __device__ __forceinline__ void cpwait(){ asm volatile("cp.async.wait_group %0;"::"n"(N):"memory"); }

// exact 2^d for d <= 0 (two-factor; flush below 2^-252)
__device__ __forceinline__ float pow2m(int d){
    if (d <= -252) return 0.0f;
    int d1 = d >> 1;
    int d2 = d - d1;
    return __int_as_float((127 + d1) << 23) * __int_as_float((127 + d2) << 23);
}

__device__ __forceinline__ void issue_group(int q, int Tin, const float* __restrict__ yp,
                                            float (*ring)[CC], int tid)
{
    for (int c = tid; c < KSTEP * 32; c += NTHR) {
        int r  = c >> 5, ch = c & 31;
        int rg = q * KSTEP + r;
        if (rg < Tin)
            cp16(&ring[rg & (RING - 1)][ch * 4], yp + (size_t)rg * CC + ch * 4);
    }
    cpcommit();
}

__global__ __launch_bounds__(NTHR, 1)
void ctc_loss_kernel(const int* __restrict__ y_true,
                     const float* __restrict__ y_pred,
                     const int* __restrict__ input_len,
                     const int* __restrict__ label_len,
                     float* __restrict__ out)
{
    __shared__ __align__(16) float ring[RING][CC];
    __shared__ float sbuf[2][SPAN];
    __shared__ int   sbE[2][LIMAX];

    const int b    = blockIdx.x;
    const int tid  = threadIdx.x;
    const int w    = tid >> 5;
    const int lane = tid & 31;

    int Tin = input_len[b];
    if (Tin > TT) Tin = TT;
    if (Tin < 0)  Tin = 0;

    const int base = w * STRIDE;
    const int s0   = base + 2 * lane;
    const int li   = (base >> 1) + lane;
    const int liC  = (li < LL) ? li : (LL - 1);
    const int ext_odd = y_true[b * LL + liC];
    float skipm = 0.0f;
    if (li >= 1 && li < LL && ext_odd != y_true[b * LL + li - 1]) skipm = 1.0f;
    const bool w0l0 = (tid == 0);

    const float* __restrict__ yp_b = y_pred + (size_t)b * TT * CC;

    float xE = (s0 == 0) ? 1.0f : 0.0f;
    float xO = 0.0f;
    int   Ei = 0;

    sbuf[1][s0] = (s0 == 0) ? 0.0f : NEGF;
    sbuf[1][s0 + 1] = NEGF;

    issue_group(0, Tin, yp_b, ring, tid);
    issue_group(1, Tin, yp_b, ring, tid);
    issue_group(2, Tin, yp_b, ring, tid);
    cpwait<2>();
    __syncthreads();

    const int nph = (Tin + KSTEP - 1) / KSTEP;

    for (int ph = 0; ph < nph; ph++) {
        const int t0   = ph * KSTEP;
        const int kmax = (Tin - t0 < KSTEP) ? (Tin - t0) : KSTEP;
        const bool lastp = (ph == nph - 1);

        #pragma unroll
        for (int k = 0; k < KSTEP; k++) {
            if (k >= kmax) break;
            const float* rp = ring[(t0 + k) & (RING - 1)];
            float pB  = rp[CC - 1] + EPSF;
            float pO  = rp[ext_odd] + EPSF;
            float pm1 = __shfl_up_sync(0xffffffffu, xO, 1);
            int   Ep  = __shfl_up_sync(0xffffffffu, Ei, 1);
            if (w0l0) pm1 = 0.0f;
            bool alive = (__float_as_int(fmaxf(xE, xO)) > 0);
            int En; float ss;
            if (alive) { En = (Ei > Ep) ? Ei : Ep; ss = pow2m(Ei - En); }
            else       { En = Ep; ss = 0.0f; }
            float sp  = pow2m(Ep - En);
            float xEs = xE * ss, xOs = xO * ss;
            float pm  = pm1 * sp;
            xE = pB * (xEs + pm);
            xO = pO * fmaf(skipm, pm, xOs + xEs);
            Ei = En;
            if ((k & 3) == 3) {
                int mb = __float_as_int(fmaxf(xE, xO));
                if (mb > 0) {
                    int e  = (mb >> 23) - 127;
                    float sc = __int_as_float((127 - e) << 23);
                    xE *= sc; xO *= sc; Ei += e;
                }
            }
        }

        float* sb = sbuf[ph & 1];
        int*   se = sbE[ph & 1];
        if (!lastp) {
            if (lane >= 24) { sb[s0] = xE; sb[s0 + 1] = xO; se[li] = Ei; }
        } else {
            float fE = (float)Ei;
            float lE = fmaxf(lg2f(xE) + fE, NEGF);
            float lO = fmaxf(lg2f(xO) + fE, NEGF);
            if (w == 0 || lane >= kmax) { sb[s0] = lE; sb[s0 + 1] = lO; }
        }

        cpwait<1>();
        __syncthreads();
        issue_group(ph + 3, Tin, yp_b, ring, tid);

        if (!lastp && w > 0 && lane < 8) {
            xE = sb[s0]; xO = sb[s0 + 1]; Ei = se[li];
        }
    }

    cpwait<0>();
    __syncthreads();

    if (tid == 0) {
        int lab = label_len[b];
        if (lab < 0)  lab = 0;
        if (lab > LL) lab = LL;
        const float* fin = sbuf[(nph - 1) & 1];
        float aL = fin[2 * lab];
        int ip = 2 * lab - 1; if (ip < 0) ip = 0;
        float aP = fin[ip];
        float mm = fmaxf(aL, aP);
        out[b] = -LN2F * (mm + lg2f(ex2f(aL - mm) + ex2f(aP - mm)));
    }
}

extern "C" void kernel_launch(void* const* d_in, const int* in_sizes, int n_in,
                              void* d_out, int out_size) {
    const int*   y_true    = nullptr;
    const float* y_pred    = nullptr;
    const int*   input_len = nullptr;
    const int*   label_len = nullptr;
    for (int i = 0; i < n_in; ++i) {
        if (in_sizes[i] == BB * TT * CC)      y_pred = (const float*)d_in[i];
        else if (in_sizes[i] == BB * LL)      y_true = (const int*)d_in[i];
        else if (in_sizes[i] == BB) {
            if (!input_len) input_len = (const int*)d_in[i];
            else            label_len = (const int*)d_in[i];
        }
    }
    ctc_loss_kernel<<<BB, NTHR>>>(y_true, y_pred, input_len, label_len, (float*)d_out);
}

// round 8
// speedup vs baseline: 1.3156x; 1.3156x over previous
#include <cuda_runtime.h>

#define BB 128
#define TT 1024
#define CC 128
#define LL 128
#define SS 257
#define EPSF 1e-7f
#define NEGF -1e30f
#define LN2F 0.69314718055994530942f
#define KSTEP 8           // DP steps per phase
#define STRIDE 112        // warp state stride = 128 - 2*KSTEP
#define RING 32           // prob rows in cp.async ring (4 phases)
#define SPAN 352          // 2*STRIDE + 128
#define NTHR 96
#define NW 3

__device__ __forceinline__ float ex2f(float x){ float y; asm("ex2.approx.ftz.f32 %0,%1;":"=f"(y):"f"(x)); return y; }
__device__ __forceinline__ float lg2f(float x){ float y; asm("lg2.approx.f32 %0,%1;":"=f"(y):"f"(x)); return y; }
__device__ __forceinline__ void cp16(void* s, const void* g){
    unsigned sa = (unsigned)__cvta_generic_to_shared(s);
    asm volatile("cp.async.cg.shared.global [%0],[%1],16;"::"r"(sa),"l"(g):"memory");
}
__device__ __forceinline__ void cpcommit(){ asm volatile("cp.async.commit_group;":::"memory"); }
template<int N> __device__ __forceinline__ void cpwait(){ asm volatile("cp.async.wait_group %0;"::"n"(N):"memory"); }

// exact 2^d for d in [-126, 0]; flushes to 0 for d <= -127 (clamped, branchless)
__device__ __forceinline__ float sc2(int d){
    int t = 127 + d;
    t = (t > 0) ? t : 0;
    return __int_as_float(t << 23);
}

__device__ __forceinline__ void issue_group(int q, int Tin, const float* __restrict__ yp,
                                            float (*ring)[CC], int tid)
{
    for (int c = tid; c < KSTEP * 32; c += NTHR) {
        int r  = c >> 5, ch = c & 31;
        int rg = q * KSTEP + r;
        if (rg < Tin)
            cp16(&ring[rg & (RING - 1)][ch * 4], yp + (size_t)rg * CC + ch * 4);
    }
    cpcommit();
}

__global__ __launch_bounds__(NTHR, 1)
void ctc_loss_kernel(const int* __restrict__ y_true,
                     const float* __restrict__ y_pred,
                     const int* __restrict__ input_len,
                     const int* __restrict__ label_len,
                     float* __restrict__ out)
{
    __shared__ __align__(16) float ring[RING][CC];
    __shared__ float sbuf[2][SPAN];
    __shared__ int   sbE[2][128];

    const int b    = blockIdx.x;
    const int tid  = threadIdx.x;
    const int w    = tid >> 5;
    const int lane = tid & 31;

    int Tin = input_len[b];
    if (Tin > TT) Tin = TT;
    if (Tin < 0)  Tin = 0;

    const int base = w * STRIDE;
    const int s0   = base + 4 * lane;           // first of 4 owned states
    const int li0  = (base >> 1) + 2 * lane;    // label idx of odd state s0+1
    const int li1  = li0 + 1;                   // label idx of odd state s0+3
    const int* yt  = y_true + b * LL;
    const int cl0  = (li0 < LL) ? li0 : (LL - 1);
    const int cl1  = (li1 < LL) ? li1 : (LL - 1);
    const int ext0 = yt[cl0];
    const int ext1 = yt[cl1];
    float skip0 = 0.0f, skip1 = 0.0f;
    if (li0 >= 1 && li0 < LL && ext0 != yt[li0 - 1]) skip0 = 1.0f;
    if (li1 < LL && ext1 != ext0)                    skip1 = 1.0f;
    const bool w0l0 = (tid == 0);

    const float* __restrict__ yp_b = y_pred + (size_t)b * TT * CC;

    // alpha = x * 2^Ei, per-lane exponent; 4 states/lane
    float xE0 = (s0 == 0) ? 1.0f : 0.0f;
    float xO0 = 0.0f, xE1 = 0.0f, xO1 = 0.0f;
    int   Ei  = 0;

    // Tin==0 fallback stash (epilogue reads sbuf[(nph-1)&1] = sbuf[1] when nph==0)
    #pragma unroll
    for (int j = 0; j < 4; j++) {
        int s = s0 + j;
        if (s < SS) sbuf[1][s] = (s == 0) ? 0.0f : NEGF;
    }

    issue_group(0, Tin, yp_b, ring, tid);
    issue_group(1, Tin, yp_b, ring, tid);
    issue_group(2, Tin, yp_b, ring, tid);
    cpwait<2>();
    __syncthreads();

    const int nph = (Tin + KSTEP - 1) / KSTEP;

    for (int ph = 0; ph < nph; ph++) {
        const int t0   = ph * KSTEP;
        const int kmax = (Tin - t0 < KSTEP) ? (Tin - t0) : KSTEP;
        const bool lastp = (ph == nph - 1);
        const int par  = ph & 1;

        // ---- preload this phase's emission probs into registers (off-chain) ----
        float pB[KSTEP], p0[KSTEP], p1[KSTEP];
        if (kmax == KSTEP) {
            #pragma unroll
            for (int k = 0; k < KSTEP; k++) {
                const float* rp = ring[(t0 + k) & (RING - 1)];
                pB[k] = rp[CC - 1] + EPSF;
                p0[k] = rp[ext0]   + EPSF;
                p1[k] = rp[ext1]   + EPSF;
            }
        } else {
            for (int k = 0; k < kmax; k++) {
                const float* rp = ring[(t0 + k) & (RING - 1)];
                pB[k] = rp[CC - 1] + EPSF;
                p0[k] = rp[ext0]   + EPSF;
                p1[k] = rp[ext1]   + EPSF;
            }
        }

        // ---- DP steps ----
        #pragma unroll
        for (int k = 0; k < KSTEP; k++) {
            if (k >= kmax) break;
            float pm = __shfl_up_sync(0xffffffffu, xO1, 1);
            int   Ep = __shfl_up_sync(0xffffffffu, Ei, 1);
            if (w0l0) pm = 0.0f;
            float mx = fmaxf(fmaxf(xE0, xO0), fmaxf(xE1, xO1));
            bool alive = (__float_as_int(mx) > 0);
            int  En = alive ? ((Ei > Ep) ? Ei : Ep) : Ep;
            float ss = alive ? sc2(Ei - En) : 0.0f;   // dead: x=0, avoid 0*inf
            float sp = sc2(Ep - En);
            float pmS = pm * sp;
            float e0 = xE0 * ss, o0 = xO0 * ss, e1 = xE1 * ss, o1 = xO1 * ss;
            xE0 = pB[k] * (e0 + pmS);
            xO0 = p0[k] * fmaf(skip0, pmS, o0 + e0);
            xE1 = pB[k] * (e1 + o0);
            xO1 = p1[k] * fmaf(skip1, o0, o1 + e1);
            Ei = En;
            if (k & 1) {                               // per-lane pow2 renorm, every 2 steps
                int mb = __float_as_int(fmaxf(fmaxf(xE0, xO0), fmaxf(xE1, xO1)));
                if (mb > 0) {
                    int e = (mb >> 23) - 127;
                    float sc = __int_as_float((127 - e) << 23);
                    xE0 *= sc; xO0 *= sc; xE1 *= sc; xO1 *= sc;
                    Ei += e;
                }
            }
        }

        // ---- phase-end exchange ----
        if (!lastp) {
            if (lane >= 28) {                          // halo for next warp's lanes 0..3
                sbuf[par][s0]     = xE0;
                sbuf[par][s0 + 1] = xO0;
                sbuf[par][s0 + 2] = xE1;
                sbuf[par][s0 + 3] = xO1;
                sbE[par][w * 28 + lane] = Ei;
            }
        } else {
            float fE = (float)Ei;
            float l0 = fmaxf(lg2f(xE0) + fE, NEGF);
            float l1 = fmaxf(lg2f(xO0) + fE, NEGF);
            float l2 = fmaxf(lg2f(xE1) + fE, NEGF);
            float l3 = fmaxf(lg2f(xO1) + fE, NEGF);
            int vmin = base + 2 * kmax;                // w>0: states below this are stale
            if (s0     < SS && (w == 0 || s0     >= vmin)) sbuf[par][s0]     = l0;
            if (s0 + 1 < SS && (w == 0 || s0 + 1 >= vmin)) sbuf[par][s0 + 1] = l1;
            if (s0 + 2 < SS && (w == 0 || s0 + 2 >= vmin)) sbuf[par][s0 + 2] = l2;
            if (s0 + 3 < SS && (w == 0 || s0 + 3 >= vmin)) sbuf[par][s0 + 3] = l3;
        }

        cpwait<1>();            // next phase's rows landed
        __syncthreads();        // publish sbuf/sbE + ring rows
        issue_group(ph + 3, Tin, yp_b, ring, tid);

        if (!lastp && w > 0 && lane < 4) {             // refresh left halo
            xE0 = sbuf[par][s0];
            xO0 = sbuf[par][s0 + 1];
            xE1 = sbuf[par][s0 + 2];
            xO1 = sbuf[par][s0 + 3];
            Ei  = sbE[par][w * 28 + lane];
        }
    }

    cpwait<0>();
    __syncthreads();

    if (tid == 0) {
        int lab = label_len[b];
        if (lab < 0)  lab = 0;
        if (lab > LL) lab = LL;
        const float* fin = sbuf[(nph - 1) & 1];
        float aL = fin[2 * lab];
        int ip = 2 * lab - 1; if (ip < 0) ip = 0;
        float aP = fin[ip];
        float mm = fmaxf(aL, aP);
        out[b] = -LN2F * (mm + lg2f(ex2f(aL - mm) + ex2f(aP - mm)));
    }
}

extern "C" void kernel_launch(void* const* d_in, const int* in_sizes, int n_in,
                              void* d_out, int out_size) {
    const int*   y_true    = nullptr;
    const float* y_pred    = nullptr;
    const int*   input_len = nullptr;
    const int*   label_len = nullptr;
    for (int i = 0; i < n_in; ++i) {
        if (in_sizes[i] == BB * TT * CC)      y_pred = (const float*)d_in[i];
        else if (in_sizes[i] == BB * LL)      y_true = (const int*)d_in[i];
        else if (in_sizes[i] == BB) {
            if (!input_len) input_len = (const int*)d_in[i];
            else            label_len = (const int*)d_in[i];
        }
    }
    ctc_loss_kernel<<<BB, NTHR>>>(y_true, y_pred, input_len, label_len, (float*)d_out);
}

// round 10
// speedup vs baseline: 1.4637x; 1.1126x over previous
#include <cuda_runtime.h>

#define BB 128
#define TT 1024
#define CC 128
#define LL 128
#define SS 257
#define EPSF 1e-7f
#define NEGF -1e30f
#define LN2F 0.69314718055994530942f
#define KSTEP 8           // DP steps per phase
#define STRIDE 112        // warp state stride = 128 - 2*KSTEP
#define RING 32           // prob rows in cp.async ring (4 phases)
#define SPAN 352          // 2*STRIDE + 128
#define NTHR 96
#define NW 3

__device__ __forceinline__ float ex2f(float x){ float y; asm("ex2.approx.ftz.f32 %0,%1;":"=f"(y):"f"(x)); return y; }
__device__ __forceinline__ float lg2f(float x){ float y; asm("lg2.approx.f32 %0,%1;":"=f"(y):"f"(x)); return y; }
__device__ __forceinline__ void cp16(void* s, const void* g){
    unsigned sa = (unsigned)__cvta_generic_to_shared(s);
    asm volatile("cp.async.cg.shared.global [%0],[%1],16;"::"r"(sa),"l"(g):"memory");
}
__device__ __forceinline__ void cpcommit(){ asm volatile("cp.async.commit_group;":::"memory"); }
template<int N> __device__ __forceinline__ void cpwait(){ asm volatile("cp.async.wait_group %0;"::"n"(N):"memory"); }

// exact 2^d for d in [-126, 0]; 0 for d <= -127 (branchless clamp)
__device__ __forceinline__ float sc2(int d){
    int t = 127 + d;
    t = (t > 0) ? t : 0;
    return __int_as_float(t << 23);
}

__device__ __forceinline__ void issue_group(int q, int Tin, const float* __restrict__ yp,
                                            float (*ring)[CC], int tid)
{
    for (int c = tid; c < KSTEP * 32; c += NTHR) {
        int r  = c >> 5, ch = c & 31;
        int rg = q * KSTEP + r;
        if (rg < Tin)
            cp16(&ring[rg & (RING - 1)][ch * 4], yp + (size_t)rg * CC + ch * 4);
    }
    cpcommit();
}

__global__ __launch_bounds__(NTHR, 1)
void ctc_loss_kernel(const int* __restrict__ y_true,
                     const float* __restrict__ y_pred,
                     const int* __restrict__ input_len,
                     const int* __restrict__ label_len,
                     float* __restrict__ out)
{
    __shared__ __align__(16) float ring[RING][CC];
    __shared__ float sbuf[2][SPAN];
    __shared__ int   sbE[2][128];

    const int b    = blockIdx.x;
    const int tid  = threadIdx.x;
    const int w    = tid >> 5;
    const int lane = tid & 31;

    int Tin = input_len[b];
    if (Tin > TT) Tin = TT;
    if (Tin < 0)  Tin = 0;

    const int base = w * STRIDE;
    const int s0   = base + 4 * lane;
    const int li0  = (base >> 1) + 2 * lane;
    const int li1  = li0 + 1;
    const int* yt  = y_true + b * LL;
    const int cl0  = (li0 < LL) ? li0 : (LL - 1);
    const int cl1  = (li1 < LL) ? li1 : (LL - 1);
    const int ext0 = yt[cl0];
    const int ext1 = yt[cl1];
    float skip0 = 0.0f, skip1 = 0.0f;
    if (li0 >= 1 && li0 < LL && ext0 != yt[li0 - 1]) skip0 = 1.0f;
    if (li1 < LL && ext1 != ext0)                    skip1 = 1.0f;
    const bool w0l0 = (tid == 0);

    const float* __restrict__ yp_b = y_pred + (size_t)b * TT * CC;

    // alpha = x * 2^Ei; dead lanes tracked by alive-gating (R8 semantics)
    float xE0 = (s0 == 0) ? 1.0f : 0.0f;
    float xO0 = 0.0f, xE1 = 0.0f, xO1 = 0.0f;
    int   Ei  = 0;

    // Tin==0 fallback stash (epilogue reads sbuf[(nph-1)&1] = sbuf[1] when nph==0)
    #pragma unroll
    for (int j = 0; j < 4; j++) {
        int s = s0 + j;
        if (s < SS) sbuf[1][s] = (s == 0) ? 0.0f : NEGF;
    }

    issue_group(0, Tin, yp_b, ring, tid);
    issue_group(1, Tin, yp_b, ring, tid);
    issue_group(2, Tin, yp_b, ring, tid);
    cpwait<2>();
    __syncthreads();

    const int nph = (Tin + KSTEP - 1) / KSTEP;

    // boundary shfl: establish pm/Ep for step 0
    float pm_in = __shfl_up_sync(0xffffffffu, xO1, 1);
    int   Ep_in = __shfl_up_sync(0xffffffffu, Ei, 1);
    if (w0l0) pm_in = 0.0f;

    for (int ph = 0; ph < nph; ph++) {
        const int t0   = ph * KSTEP;
        const int kmax = (Tin - t0 < KSTEP) ? (Tin - t0) : KSTEP;
        const bool lastp = (ph == nph - 1);
        const int par  = ph & 1;

        if (kmax == KSTEP) {
            // preload this phase's emissions (off the dependent chain)
            float pB[KSTEP], p0[KSTEP], p1[KSTEP];
            #pragma unroll
            for (int k = 0; k < KSTEP; k++) {
                const float* rp = ring[(t0 + k) & (RING - 1)];
                pB[k] = rp[CC - 1] + EPSF;
                p0[k] = rp[ext0]   + EPSF;
                p1[k] = rp[ext1]   + EPSF;
            }
            // straight-line 8 steps, no per-step branch
            #pragma unroll
            for (int k = 0; k < KSTEP; k++) {
                // alive from step-entry values: parallel to the incoming shfl
                float mx = fmaxf(fmaxf(xE0, xO0), fmaxf(xE1, xO1));
                bool alive = (__float_as_int(mx) > 0);
                int  En = alive ? ((Ei > Ep_in) ? Ei : Ep_in) : Ep_in;
                float ss = alive ? sc2(Ei - En) : 0.0f;  // dead lane adopts left's frame
                float sp = sc2(Ep_in - En);
                float pmS = pm_in * sp;
                float e0 = xE0 * ss, o0 = xO0 * ss, e1 = xE1 * ss, o1 = xO1 * ss;
                xE0 = pB[k] * (e0 + pmS);
                xO0 = p0[k] * fmaf(skip0, pmS, o0 + e0);
                xE1 = pB[k] * (e1 + o0);
                xO1 = p1[k] * fmaf(skip1, o0, o1 + e1);
                Ei = En;
                if (k < KSTEP - 1) {
                    // early shfl (pre-renorm (value,exp) pair is frame-consistent);
                    // its 26-cyc latency overlaps the renorm below
                    pm_in = __shfl_up_sync(0xffffffffu, xO1, 1);
                    Ep_in = __shfl_up_sync(0xffffffffu, Ei, 1);
                    if (w0l0) pm_in = 0.0f;
                }
                if (k & 1) {                  // per-lane pow2 renorm every 2 steps
                    int mb = __float_as_int(fmaxf(fmaxf(xE0, xO0), fmaxf(xE1, xO1)));
                    if (mb > 0) {
                        int e = (mb >> 23) - 127;
                        float sc = __int_as_float((127 - e) << 23);
                        xE0 *= sc; xO0 *= sc; xE1 *= sc; xO1 *= sc;
                        Ei += e;
                    }
                }
            }
        } else {
            // tail phase (at most once, final partial phase)
            for (int k = 0; k < kmax; k++) {
                const float* rp = ring[(t0 + k) & (RING - 1)];
                float pBt = rp[CC - 1] + EPSF;
                float p0t = rp[ext0]   + EPSF;
                float p1t = rp[ext1]   + EPSF;
                float pm = __shfl_up_sync(0xffffffffu, xO1, 1);
                int   Ep = __shfl_up_sync(0xffffffffu, Ei, 1);
                if (w0l0) pm = 0.0f;
                float mx = fmaxf(fmaxf(xE0, xO0), fmaxf(xE1, xO1));
                bool alive = (__float_as_int(mx) > 0);
                int  En = alive ? ((Ei > Ep) ? Ei : Ep) : Ep;
                float ss = alive ? sc2(Ei - En) : 0.0f;
                float sp = sc2(Ep - En);
                float pmS = pm * sp;
                float e0 = xE0 * ss, o0 = xO0 * ss, e1 = xE1 * ss, o1 = xO1 * ss;
                xE0 = pBt * (e0 + pmS);
                xO0 = p0t * fmaf(skip0, pmS, o0 + e0);
                xE1 = pBt * (e1 + o0);
                xO1 = p1t * fmaf(skip1, o0, o1 + e1);
                Ei = En;
                int mb = __float_as_int(fmaxf(fmaxf(xE0, xO0), fmaxf(xE1, xO1)));
                if (mb > 0) {
                    int e = (mb >> 23) - 127;
                    float sc = __int_as_float((127 - e) << 23);
                    xE0 *= sc; xO0 *= sc; xE1 *= sc; xO1 *= sc;
                    Ei += e;
                }
            }
        }

        // ---- phase-end exchange ----
        if (!lastp) {
            if (lane >= 28) {
                sbuf[par][s0]     = xE0;
                sbuf[par][s0 + 1] = xO0;
                sbuf[par][s0 + 2] = xE1;
                sbuf[par][s0 + 3] = xO1;
                sbE[par][w * 28 + lane] = Ei;
            }
        } else {
            float fE = (float)Ei;
            float l0 = fmaxf(lg2f(xE0) + fE, NEGF);
            float l1 = fmaxf(lg2f(xO0) + fE, NEGF);
            float l2 = fmaxf(lg2f(xE1) + fE, NEGF);
            float l3 = fmaxf(lg2f(xO1) + fE, NEGF);
            int vmin = base + 2 * kmax;
            if (s0     < SS && (w == 0 || s0     >= vmin)) sbuf[par][s0]     = l0;
            if (s0 + 1 < SS && (w == 0 || s0 + 1 >= vmin)) sbuf[par][s0 + 1] = l1;
            if (s0 + 2 < SS && (w == 0 || s0 + 2 >= vmin)) sbuf[par][s0 + 2] = l2;
            if (s0 + 3 < SS && (w == 0 || s0 + 3 >= vmin)) sbuf[par][s0 + 3] = l3;
        }

        cpwait<1>();
        __syncthreads();
        issue_group(ph + 3, Tin, yp_b, ring, tid);

        if (!lastp) {
            if (w > 0 && lane < 4) {           // refresh left halo
                xE0 = sbuf[par][s0];
                xO0 = sbuf[par][s0 + 1];
                xE1 = sbuf[par][s0 + 2];
                xO1 = sbuf[par][s0 + 3];
                Ei  = sbE[par][w * 28 + lane];
            }
            // boundary shfl with refreshed values (lane 4 needs lane 3's new xO1)
            pm_in = __shfl_up_sync(0xffffffffu, xO1, 1);
            Ep_in = __shfl_up_sync(0xffffffffu, Ei, 1);
            if (w0l0) pm_in = 0.0f;
        }
    }

    cpwait<0>();
    __syncthreads();

    if (tid == 0) {
        int lab = label_len[b];
        if (lab < 0)  lab = 0;
        if (lab > LL) lab = LL;
        const float* fin = sbuf[(nph - 1) & 1];
        float aL = fin[2 * lab];
        int ip = 2 * lab - 1; if (ip < 0) ip = 0;
        float aP = fin[ip];
        float mm = fmaxf(aL, aP);
        out[b] = -LN2F * (mm + lg2f(ex2f(aL - mm) + ex2f(aP - mm)));
    }
}

extern "C" void kernel_launch(void* const* d_in, const int* in_sizes, int n_in,
                              void* d_out, int out_size) {
    const int*   y_true    = nullptr;
    const float* y_pred    = nullptr;
    const int*   input_len = nullptr;
    const int*   label_len = nullptr;
    for (int i = 0; i < n_in; ++i) {
        if (in_sizes[i] == BB * TT * CC)      y_pred = (const float*)d_in[i];
        else if (in_sizes[i] == BB * LL)      y_true = (const int*)d_in[i];
        else if (in_sizes[i] == BB) {
            if (!input_len) input_len = (const int*)d_in[i];
            else            label_len = (const int*)d_in[i];
        }
    }
    ctc_loss_kernel<<<BB, NTHR>>>(y_true, y_pred, input_len, label_len, (float*)d_out);
}

// round 11
// speedup vs baseline: 1.8547x; 1.2671x over previous
#include <cuda_runtime.h>

#define BB 128
#define TT 1024
#define CC 128
#define LL 128
#define SS 257
#define EPSF 1e-7f
#define NEGF -1e30f
#define LN2F 0.69314718055994530942f
#define KSTEP 8           // frames per phase
#define STRIDE 112        // warp state stride = 128 - 2*KSTEP
#define RING 32           // prob rows in cp.async ring (4 phases)
#define SPAN 352          // 2*STRIDE + 128
#define NTHR 96
#define NW 3

__device__ __forceinline__ float ex2f(float x){ float y; asm("ex2.approx.ftz.f32 %0,%1;":"=f"(y):"f"(x)); return y; }
__device__ __forceinline__ float lg2f(float x){ float y; asm("lg2.approx.f32 %0,%1;":"=f"(y):"f"(x)); return y; }
__device__ __forceinline__ void cp16(void* s, const void* g){
    unsigned sa = (unsigned)__cvta_generic_to_shared(s);
    asm volatile("cp.async.cg.shared.global [%0],[%1],16;"::"r"(sa),"l"(g):"memory");
}
__device__ __forceinline__ void cpcommit(){ asm volatile("cp.async.commit_group;":::"memory"); }
template<int N> __device__ __forceinline__ void cpwait(){ asm volatile("cp.async.wait_group %0;"::"n"(N):"memory"); }

// exact 2^d for d in [-126, 0]; 0 for d <= -127 (branchless clamp)
__device__ __forceinline__ float sc2(int d){
    int t = 127 + d;
    t = (t > 0) ? t : 0;
    return __int_as_float(t << 23);
}

__device__ __forceinline__ void issue_group(int q, int Tin, const float* __restrict__ yp,
                                            float (*ring)[CC], int tid)
{
    for (int c = tid; c < KSTEP * 32; c += NTHR) {
        int r  = c >> 5, ch = c & 31;
        int rg = q * KSTEP + r;
        if (rg < Tin)
            cp16(&ring[rg & (RING - 1)][ch * 4], yp + (size_t)rg * CC + ch * 4);
    }
    cpcommit();
}

__global__ __launch_bounds__(NTHR, 1)
void ctc_loss_kernel(const int* __restrict__ y_true,
                     const float* __restrict__ y_pred,
                     const int* __restrict__ input_len,
                     const int* __restrict__ label_len,
                     float* __restrict__ out)
{
    __shared__ __align__(16) float ring[RING][CC];
    __shared__ float sbuf[2][SPAN];
    __shared__ int   sbE[2][128];

    const int b    = blockIdx.x;
    const int tid  = threadIdx.x;
    const int w    = tid >> 5;
    const int lane = tid & 31;

    int Tin = input_len[b];
    if (Tin > TT) Tin = TT;
    if (Tin < 0)  Tin = 0;

    const int base = w * STRIDE;
    const int s0   = base + 4 * lane;
    const int li0  = (base >> 1) + 2 * lane;   // label idx of odd state s0+1
    const int li1  = li0 + 1;                  // label idx of odd state s0+3
    const int liM  = li0 - 1;                  // label idx of odd state s0-1 (left lane)
    const int* yt  = y_true + b * LL;
    const int cl0  = (li0 < LL) ? li0 : (LL - 1);
    const int cl1  = (li1 < LL) ? li1 : (LL - 1);
    int clM = liM; if (clM < 0) clM = 0; if (clM > LL - 1) clM = LL - 1;
    const int ext0 = yt[cl0];
    const int ext1 = yt[cl1];
    const int extM = yt[clM];
    float skip0 = 0.0f, skip1 = 0.0f, skipM = 0.0f;
    if (li0 >= 1 && li0 < LL && ext0 != yt[li0 - 1]) skip0 = 1.0f;
    if (li1 < LL && ext1 != ext0)                    skip1 = 1.0f;
    if (liM >= 1 && liM < LL && extM != yt[liM - 1]) skipM = 1.0f;
    const bool w0l0 = (tid == 0);

    const float* __restrict__ yp_b = y_pred + (size_t)b * TT * CC;

    // alpha = x * 2^Ei; states per lane: D=xE0(s0) E=xO0(s0+1) F=xE1(s0+2) G=xO1(s0+3)
    float xE0 = (s0 == 0) ? 1.0f : 0.0f;
    float xO0 = 0.0f, xE1 = 0.0f, xO1 = 0.0f;
    int   Ei  = 0;
    bool  alive = (tid == 0);

    // Tin==0 fallback stash
    #pragma unroll
    for (int j = 0; j < 4; j++) {
        int s = s0 + j;
        if (s < SS) sbuf[1][s] = (s == 0) ? 0.0f : NEGF;
    }

    issue_group(0, Tin, yp_b, ring, tid);
    issue_group(1, Tin, yp_b, ring, tid);
    issue_group(2, Tin, yp_b, ring, tid);
    cpwait<2>();
    __syncthreads();

    const int nph = (Tin + KSTEP - 1) / KSTEP;

    // boundary shfl: incoming A=left xO0 (s0-3), Bv=left xE1 (s0-2), Cv=left xO1 (s0-1)
    float A  = __shfl_up_sync(0xffffffffu, xO0, 1);
    float Bv = __shfl_up_sync(0xffffffffu, xE1, 1);
    float Cv = __shfl_up_sync(0xffffffffu, xO1, 1);
    int   Ep = __shfl_up_sync(0xffffffffu, Ei, 1);

    for (int ph = 0; ph < nph; ph++) {
        const int t0   = ph * KSTEP;
        const int kmax = (Tin - t0 < KSTEP) ? (Tin - t0) : KSTEP;
        const bool lastp = (ph == nph - 1);
        const int par  = ph & 1;

        if (kmax == KSTEP) {
            // preload emissions (off the dependent chain)
            float pB[KSTEP], p0[KSTEP], p1[KSTEP], pM[KSTEP / 2];
            #pragma unroll
            for (int k = 0; k < KSTEP; k++) {
                const float* rp = ring[(t0 + k) & (RING - 1)];
                pB[k] = rp[CC - 1] + EPSF;
                p0[k] = rp[ext0]   + EPSF;
                p1[k] = rp[ext1]   + EPSF;
            }
            #pragma unroll
            for (int j = 0; j < KSTEP / 2; j++)
                pM[j] = ring[(t0 + 2 * j) & (RING - 1)][extM] + EPSF;

            // 4 fused iterations = 8 frames, straight-line
            #pragma unroll
            for (int j = 0; j < KSTEP / 2; j++) {
                const int k0 = 2 * j, k1 = 2 * j + 1;
                // own-frame sums (independent of incoming shfl)
                float q1  = xO0 + xE0;                 // E+D
                float q2  = xE1 + xO0;                 // F+E
                float q3  = xO1 + xE1;                 // G+F
                float t3o = fmaf(skip1, xO0, q3);      // G+F+s1*E
                float t1o = fmaf(skipM, A, Bv + Cv);   // C+B+sm*A (incoming frame)
                // frame resolution (alive pred carried from prior renorm: off-chain)
                int   En = alive ? ((Ei > Ep) ? Ei : Ep) : Ep;
                float ss = alive ? sc2(Ei - En) : 0.0f;
                float sp = w0l0 ? 0.0f : sc2(Ep - En);
                float Cs = Cv * sp;
                float t1 = t1o * sp;
                float X1 = pM[j] * t1;                 // pm0*(C+B+sm*A)
                float u1 = fmaf(xE0, ss, Cs);          // D+C
                float Y1 = pB[k0] * u1;
                float t2 = fmaf(q1, ss, skip0 * Cs);   // E+D+s0*C
                float X2 = p0[k0] * t2;
                float Y2 = pB[k0] * (q2 * ss);
                float X3 = p1[k0] * (t3o * ss);
                xE0 = pB[k1] * (Y1 + X1);
                xO0 = p0[k1] * fmaf(skip0, X1, X2 + Y1);
                xE1 = pB[k1] * (Y2 + X2);
                xO1 = p1[k1] * fmaf(skip1, X2, X3 + Y2);
                Ei = En;
                if (j < KSTEP / 2 - 1) {
                    // early shfl (pre-renorm (value,exp) pair is frame-consistent)
                    A  = __shfl_up_sync(0xffffffffu, xO0, 1);
                    Bv = __shfl_up_sync(0xffffffffu, xE1, 1);
                    Cv = __shfl_up_sync(0xffffffffu, xO1, 1);
                    Ep = __shfl_up_sync(0xffffffffu, Ei, 1);
                }
                // per-lane pow2 renorm (once per 2 frames)
                int mb = __float_as_int(fmaxf(fmaxf(xE0, xO0), fmaxf(xE1, xO1)));
                alive = (mb > 0);
                if (alive) {
                    int e = (mb >> 23) - 127;
                    float sc = __int_as_float((127 - e) << 23);
                    xE0 *= sc; xO0 *= sc; xE1 *= sc; xO1 *= sc;
                    Ei += e;
                }
            }
        } else {
            // tail phase (at most once): R10 single-step loop verbatim
            for (int k = 0; k < kmax; k++) {
                const float* rp = ring[(t0 + k) & (RING - 1)];
                float pBt = rp[CC - 1] + EPSF;
                float p0t = rp[ext0]   + EPSF;
                float p1t = rp[ext1]   + EPSF;
                float pm = __shfl_up_sync(0xffffffffu, xO1, 1);
                int   Ex = __shfl_up_sync(0xffffffffu, Ei, 1);
                if (w0l0) pm = 0.0f;
                float mx = fmaxf(fmaxf(xE0, xO0), fmaxf(xE1, xO1));
                bool al = (__float_as_int(mx) > 0);
                int  En = al ? ((Ei > Ex) ? Ei : Ex) : Ex;
                float ss = al ? sc2(Ei - En) : 0.0f;
                float sp = sc2(Ex - En);
                float pmS = pm * sp;
                float e0 = xE0 * ss, o0 = xO0 * ss, e1 = xE1 * ss, o1 = xO1 * ss;
                xE0 = pBt * (e0 + pmS);
                xO0 = p0t * fmaf(skip0, pmS, o0 + e0);
                xE1 = pBt * (e1 + o0);
                xO1 = p1t * fmaf(skip1, o0, o1 + e1);
                Ei = En;
                int mb = __float_as_int(fmaxf(fmaxf(xE0, xO0), fmaxf(xE1, xO1)));
                if (mb > 0) {
                    int e = (mb >> 23) - 127;
                    float sc = __int_as_float((127 - e) << 23);
                    xE0 *= sc; xO0 *= sc; xE1 *= sc; xO1 *= sc;
                    Ei += e;
                }
            }
        }

        // ---- phase-end exchange ----
        if (!lastp) {
            if (lane >= 28) {
                sbuf[par][s0]     = xE0;
                sbuf[par][s0 + 1] = xO0;
                sbuf[par][s0 + 2] = xE1;
                sbuf[par][s0 + 3] = xO1;
                sbE[par][w * 28 + lane] = Ei;
            }
        } else {
            float fE = (float)Ei;
            float l0 = fmaxf(lg2f(xE0) + fE, NEGF);
            float l1 = fmaxf(lg2f(xO0) + fE, NEGF);
            float l2 = fmaxf(lg2f(xE1) + fE, NEGF);
            float l3 = fmaxf(lg2f(xO1) + fE, NEGF);
            int vmin = base + 2 * kmax;
            if (s0     < SS && (w == 0 || s0     >= vmin)) sbuf[par][s0]     = l0;
            if (s0 + 1 < SS && (w == 0 || s0 + 1 >= vmin)) sbuf[par][s0 + 1] = l1;
            if (s0 + 2 < SS && (w == 0 || s0 + 2 >= vmin)) sbuf[par][s0 + 2] = l2;
            if (s0 + 3 < SS && (w == 0 || s0 + 3 >= vmin)) sbuf[par][s0 + 3] = l3;
        }

        cpwait<1>();
        __syncthreads();
        issue_group(ph + 3, Tin, yp_b, ring, tid);

        if (!lastp) {
            if (w > 0 && lane < 4) {            // refresh left halo
                xE0 = sbuf[par][s0];
                xO0 = sbuf[par][s0 + 1];
                xE1 = sbuf[par][s0 + 2];
                xO1 = sbuf[par][s0 + 3];
                Ei  = sbE[par][w * 28 + lane];
                float mr = fmaxf(fmaxf(xE0, xO0), fmaxf(xE1, xO1));
                alive = (__float_as_int(mr) > 0);
            }
            // boundary shfl with refreshed values
            A  = __shfl_up_sync(0xffffffffu, xO0, 1);
            Bv = __shfl_up_sync(0xffffffffu, xE1, 1);
            Cv = __shfl_up_sync(0xffffffffu, xO1, 1);
            Ep = __shfl_up_sync(0xffffffffu, Ei, 1);
        }
    }

    cpwait<0>();
    __syncthreads();

    if (tid == 0) {
        int lab = label_len[b];
        if (lab < 0)  lab = 0;
        if (lab > LL) lab = LL;
        const float* fin = sbuf[(nph - 1) & 1];
        float aL = fin[2 * lab];
        int ip = 2 * lab - 1; if (ip < 0) ip = 0;
        float aP = fin[ip];
        float mm = fmaxf(aL, aP);
        out[b] = -LN2F * (mm + lg2f(ex2f(aL - mm) + ex2f(aP - mm)));
    }
}

extern "C" void kernel_launch(void* const* d_in, const int* in_sizes, int n_in,
                              void* d_out, int out_size) {
    const int*   y_true    = nullptr;
    const float* y_pred    = nullptr;
    const int*   input_len = nullptr;
    const int*   label_len = nullptr;
    for (int i = 0; i < n_in; ++i) {
        if (in_sizes[i] == BB * TT * CC)      y_pred = (const float*)d_in[i];
        else if (in_sizes[i] == BB * LL)      y_true = (const int*)d_in[i];
        else if (in_sizes[i] == BB) {
            if (!input_len) input_len = (const int*)d_in[i];
            else            label_len = (const int*)d_in[i];
        }
    }
    ctc_loss_kernel<<<BB, NTHR>>>(y_true, y_pred, input_len, label_len, (float*)d_out);
}